// round 1
// baseline (speedup 1.0000x reference)
#include <cuda_runtime.h>
#include <math.h>

#define BB 64
#define SS 4096
#define EE 50
#define TT 20
#define CS 256
#define HALO 5
#define RR (CS + 2*HALO)      // 266
#define XSTR 274
#define NPOS 34
#define NTHREADS 400
#define SMEM_FLOATS (7500 + 50 + 1000 + 20 + 2 + EE*XSTR)
#define SMEM_BYTES (SMEM_FLOATS * 4)

// scratch (allocation-free rule: device globals)
__device__ float g_em[(size_t)SS * BB * TT];            // raw emissions [s][b][t]
__device__ float g_ee[(size_t)(SS + 32) * BB * TT];     // exp(emissions), padded for prefetch overrun
__device__ float g_num[BB];
__device__ float g_den[BB];

// ---------------------------------------------------------------------------
// Fused: embedding gather -> 5x (conv1d + swish residual) -> emissions (+exp)
// grid (S/CS, B), 400 threads = (o:50) x (strip:8), dyn smem 89KB
// ---------------------------------------------------------------------------
__global__ __launch_bounds__(NTHREADS, 2)
void conv_emit_kernel(const int* __restrict__ token_id,
                      const float* __restrict__ embed_table,
                      const float* __restrict__ conv_w,
                      const float* __restrict__ conv_b,
                      const float* __restrict__ out_w,
                      const float* __restrict__ out_b)
{
    extern __shared__ float sm[];
    float* ws = sm;             // [i*3+k][o] : 7500
    float* cb = ws + 7500;      // 50
    float* ow = cb + 50;        // [t][e] : 1000
    float* ob = ow + 1000;      // 20
    float* xs = ob + 20 + 2;    // [e][XSTR] : 50*274  (+2 pad so xs[-1] is in-bounds smem)

    const int tid = threadIdx.x;
    const int b   = blockIdx.y;
    const int s0  = blockIdx.x * CS;

    // weights: transpose conv_w [o][i][k] -> ws[(i*3+k)*50 + o]
    for (int idx = tid; idx < 7500; idx += NTHREADS) {
        int o = idx / 150; int rem = idx - o * 150;
        ws[rem * 50 + o] = conv_w[idx];
    }
    for (int idx = tid; idx < 1000; idx += NTHREADS) ow[idx] = out_w[idx];
    if (tid < 50) cb[tid] = conv_b[tid];
    if (tid < 20) ob[tid] = out_b[tid];

    // embedding gather into smem (zeros outside [0,S))
    for (int idx = tid; idx < EE * RR; idx += NTHREADS) {
        int p = idx / EE; int e = idx - p * EE;
        int s = s0 - HALO + p;
        float v = 0.0f;
        if (s >= 0 && s < SS) {
            int tok = token_id[b * SS + s];
            v = embed_table[tok * EE + e];
        }
        xs[e * XSTR + p] = v;
    }
    __syncthreads();

    const int o     = tid % 50;
    const int strip = tid / 50;          // 0..7
    const int pb    = strip * NPOS;
    const float cbias = cb[o];
    const int pad_lo = (s0 == 0) ? HALO : 0;
    int pad_hi = SS - s0 + HALO; if (pad_hi > RR) pad_hi = RR;

    for (int iter = 1; iter <= 5; ++iter) {
        float acc[NPOS];
        #pragma unroll
        for (int j = 0; j < NPOS; ++j) acc[j] = 0.0f;

        #pragma unroll 1
        for (int i = 0; i < EE; ++i) {
            float w0 = ws[(i * 3 + 0) * 50 + o];
            float w1 = ws[(i * 3 + 1) * 50 + o];
            float w2 = ws[(i * 3 + 2) * 50 + o];
            const float* xr = &xs[i * XSTR + pb];
            float xm = xr[-1];
            float xc = xr[0];
            #pragma unroll
            for (int j = 0; j < NPOS; ++j) {
                float xp = xr[j + 1];
                float a = acc[j];
                a = fmaf(w0, xm, a);
                a = fmaf(w1, xc, a);
                a = fmaf(w2, xp, a);
                acc[j] = a;
                xm = xc; xc = xp;
            }
        }
        __syncthreads();

        int lo = (iter > pad_lo) ? iter : pad_lo;
        int hi = RR - iter; if (hi > pad_hi) hi = pad_hi;
        #pragma unroll
        for (int j = 0; j < NPOS; ++j) {
            int p = pb + j;
            if (p >= lo && p < hi) {
                float y = acc[j] + cbias;
                float sw = y * (1.0f / (1.0f + __expf(-y)));
                xs[o * XSTR + p] += sw;      // x = swish(y) + x
            }
        }
        __syncthreads();
    }

    // emissions for p in [HALO, HALO+CS)
    for (int idx = tid; idx < TT * CS; idx += NTHREADS) {
        int t = idx % TT;
        int q = idx / TT;          // 0..255
        int p = HALO + q;
        int s = s0 + q;
        float acc = ob[t];
        const float* owt = &ow[t * EE];
        const float* xcol = &xs[p];
        #pragma unroll 5
        for (int e = 0; e < EE; ++e) acc = fmaf(xcol[e * XSTR], owt[e], acc);
        int gi = (s * BB + b) * TT + t;
        g_em[gi] = acc;
        g_ee[gi] = __expf(acc);
    }
}

// ---------------------------------------------------------------------------
// Numerator: gold path score per batch.  grid(B), 256 threads
// ---------------------------------------------------------------------------
__global__ void numerator_kernel(const int* __restrict__ tag,
                                 const float* __restrict__ start_trans,
                                 const float* __restrict__ end_trans,
                                 const float* __restrict__ trans)
{
    __shared__ float red[256];
    const int b = blockIdx.x;
    float sum = 0.0f;
    for (int s = threadIdx.x; s < SS; s += 256) {
        int tg = tag[b * SS + s];
        sum += g_em[(s * BB + b) * TT + tg];
        if (s > 0) sum += trans[tag[b * SS + s - 1] * TT + tg];
    }
    red[threadIdx.x] = sum;
    __syncthreads();
    for (int k = 128; k > 0; k >>= 1) {
        if (threadIdx.x < k) red[threadIdx.x] += red[threadIdx.x + k];
        __syncthreads();
    }
    if (threadIdx.x == 0) {
        g_num[b] = red[0] + start_trans[tag[b * SS]] + end_trans[tag[b * SS + SS - 1]];
    }
}

// ---------------------------------------------------------------------------
// CRF forward (denominator), scaled probability-space recursion.
// One warp per batch: lane j holds beta_j and column j of exp(trans).
// ---------------------------------------------------------------------------
__device__ __forceinline__ float crf_step(float beta, const float* Et, float e)
{
    float a0 = 0.f, a1 = 0.f, a2 = 0.f, a3 = 0.f;
    #pragma unroll
    for (int i = 0; i < TT; i += 4) {
        a0 = fmaf(__shfl_sync(0xffffffffu, beta, i + 0), Et[i + 0], a0);
        a1 = fmaf(__shfl_sync(0xffffffffu, beta, i + 1), Et[i + 1], a1);
        a2 = fmaf(__shfl_sync(0xffffffffu, beta, i + 2), Et[i + 2], a2);
        a3 = fmaf(__shfl_sync(0xffffffffu, beta, i + 3), Et[i + 3], a3);
    }
    return e * ((a0 + a1) + (a2 + a3));
}

__global__ void crf_forward_kernel(const float* __restrict__ start_trans,
                                   const float* __restrict__ end_trans,
                                   const float* __restrict__ trans)
{
    const int b = blockIdx.x;
    const int j = threadIdx.x;          // 0..31
    const bool ok = (j < TT);
    const int jj = ok ? j : 0;

    float Et[TT];
    #pragma unroll
    for (int i = 0; i < TT; ++i) Et[i] = ok ? __expf(trans[i * TT + jj]) : 0.0f;

    float beta = ok ? __expf(start_trans[jj]) * g_ee[b * TT + jj] : 0.0f;
    float L = 0.0f;

    float ea[8], eb[8];
    #pragma unroll
    for (int k = 0; k < 8; ++k) ea[k] = g_ee[((1 + k) * BB + b) * TT + jj];

    const int NG = (SS - 1 + 7) / 8;    // 512, even
    for (int g = 0; g < NG; g += 2) {
        // prefetch group g+1
        int bn = 1 + (g + 1) * 8;
        #pragma unroll
        for (int k = 0; k < 8; ++k) eb[k] = g_ee[((bn + k) * BB + b) * TT + jj];
        // process group g
        int bs = 1 + g * 8;
        #pragma unroll
        for (int k = 0; k < 8; ++k) {
            if (bs + k < SS) beta = crf_step(beta, Et, ea[k]);
        }
        {   // renorm
            float m = beta;
            #pragma unroll
            for (int off = 16; off > 0; off >>= 1)
                m = fmaxf(m, __shfl_xor_sync(0xffffffffu, m, off));
            L += __log2f(m);
            beta *= __frcp_rn(m);
        }
        // prefetch group g+2
        int bn2 = 1 + (g + 2) * 8;
        #pragma unroll
        for (int k = 0; k < 8; ++k) ea[k] = g_ee[((bn2 + k) * BB + b) * TT + jj];
        // process group g+1
        #pragma unroll
        for (int k = 0; k < 8; ++k) {
            if (bn + k < SS) beta = crf_step(beta, Et, eb[k]);
        }
        {
            float m = beta;
            #pragma unroll
            for (int off = 16; off > 0; off >>= 1)
                m = fmaxf(m, __shfl_xor_sync(0xffffffffu, m, off));
            L += __log2f(m);
            beta *= __frcp_rn(m);
        }
    }

    float v = ok ? beta * __expf(end_trans[jj]) : 0.0f;
    #pragma unroll
    for (int off = 16; off > 0; off >>= 1) v += __shfl_xor_sync(0xffffffffu, v, off);
    if (j == 0) g_den[b] = (L + __log2f(v)) * 0.69314718055994531f;
}

// ---------------------------------------------------------------------------
// Final: out = sum_b (denominator_b - numerator_b) = -llh
// ---------------------------------------------------------------------------
__global__ void final_kernel(float* __restrict__ out)
{
    __shared__ float red[64];
    int t = threadIdx.x;
    red[t] = g_den[t] - g_num[t];
    __syncthreads();
    for (int k = 32; k > 0; k >>= 1) {
        if (t < k) red[t] += red[t + k];
        __syncthreads();
    }
    if (t == 0) out[0] = red[0];
}

extern "C" void kernel_launch(void* const* d_in, const int* in_sizes, int n_in,
                              void* d_out, int out_size)
{
    const int*   token_id    = (const int*)d_in[0];
    const int*   tag_id      = (const int*)d_in[1];
    const float* embed_table = (const float*)d_in[2];
    const float* conv_w      = (const float*)d_in[3];
    const float* conv_b      = (const float*)d_in[4];
    const float* out_w       = (const float*)d_in[5];
    const float* out_b       = (const float*)d_in[6];
    const float* start_trans = (const float*)d_in[7];
    const float* end_trans   = (const float*)d_in[8];
    const float* trans       = (const float*)d_in[9];

    cudaFuncSetAttribute(conv_emit_kernel,
                         cudaFuncAttributeMaxDynamicSharedMemorySize, SMEM_BYTES);

    dim3 grid(SS / CS, BB);
    conv_emit_kernel<<<grid, NTHREADS, SMEM_BYTES>>>(token_id, embed_table, conv_w,
                                                     conv_b, out_w, out_b);
    numerator_kernel<<<BB, 256>>>(tag_id, start_trans, end_trans, trans);
    crf_forward_kernel<<<BB, 32>>>(start_trans, end_trans, trans);
    final_kernel<<<1, 64>>>((float*)d_out);
}